// round 2
// baseline (speedup 1.0000x reference)
#include <cuda_runtime.h>

#define Bn   256
#define Tn   512
#define Dn   64
#define En   128
#define H1n  128
#define H2n  64
#define Vn   10000
#define ML   30
#define SOS_ 1
#define EOS_ 2

// ---------------- persistent decoder state (device globals, no allocs) --------
__device__ float g_h1[2][Bn * H1n];   // ping-pong (multiple blocks read while writing)
__device__ float g_c1[Bn * H1n];
__device__ float g_h2[Bn * H2n];
__device__ float g_c2[Bn * H2n];
__device__ float g_ctx[Bn * Dn];
__device__ float g_x[Bn * (H2n + Dn)];          // [h2 | ctx] input to pred GEMM
__device__ unsigned long long g_amax[Bn];       // packed (fkey(val)<<32 | ~v)

__device__ __forceinline__ unsigned int fkey(float f) {
    unsigned int u = __float_as_uint(f);
    return (u & 0x80000000u) ? ~u : (u | 0x80000000u);   // monotonic float->uint
}
__device__ __forceinline__ float sigm(float x) { return 1.0f / (1.0f + expf(-x)); }

// ---------------- init: zero state, tok = SOS -------------------------------
__global__ void k_init() {
    int i = blockIdx.x * blockDim.x + threadIdx.x;
    if (i < Bn * H1n) { g_h1[0][i] = 0.f; g_c1[i] = 0.f; }
    if (i < Bn * H2n) { g_h2[i] = 0.f; g_c2[i] = 0.f; }
    if (i < Bn * Dn)  { g_ctx[i] = 0.f; }
    if (i < Bn)       { g_amax[i] = (unsigned long long)(~(unsigned int)SOS_); } // decodes to tok=1
}

// ---------------- LSTM1: embed(argmax) + gates GEMM + cell update -----------
// grid (8 k-tiles of 16, 16 b-tiles of 16), 256 threads
__global__ void k_lstm1(const float* __restrict__ wih, const float* __restrict__ whh,
                        const float* __restrict__ bih, const float* __restrict__ bhh,
                        const float* __restrict__ emb, int ph) {
    __shared__ float s_in[192][16];   // [k][b]  (embed|ctx)
    __shared__ float s_h[128][16];    // [k][b]  h1
    __shared__ float s_g[16][64];     // [b][gate*16+kk]
    __shared__ int   s_tok[16];
    const float* __restrict__ h1in = g_h1[ph];
    float* __restrict__ h1out = g_h1[ph ^ 1];

    int kt = blockIdx.x, bt = blockIdx.y;
    int b0 = bt * 16;
    int tid = threadIdx.x;

    if (tid < 16) {
        unsigned long long a = g_amax[b0 + tid];
        s_tok[tid] = (int)(~(unsigned int)(a & 0xFFFFFFFFull));
    }
    __syncthreads();

    for (int idx = tid; idx < 16 * 192; idx += 256) {
        int bb = idx / 192, k = idx - bb * 192;
        float v;
        if (k < En) {
            int tok = s_tok[bb];
            v = (tok == EOS_) ? 0.f : emb[(size_t)tok * En + k];   // padding row zeroed
        } else {
            v = g_ctx[(b0 + bb) * Dn + (k - En)];
        }
        s_in[k][bb] = v;
    }
    for (int idx = tid; idx < 16 * 128; idx += 256) {
        int bb = idx >> 7, k = idx & 127;
        s_h[k][bb] = h1in[(b0 + bb) * H1n + k];
    }
    __syncthreads();

    int col = tid & 63;            // gate*16 + kk
    int bg  = tid >> 6;            // 4 b's per thread
    int gate = col >> 4, kk = col & 15;
    int j = gate * H1n + kt * 16 + kk;

    float acc[4] = {0.f, 0.f, 0.f, 0.f};
    const float4* wr = (const float4*)(wih + (size_t)j * 192);
    #pragma unroll 8
    for (int k4 = 0; k4 < 48; k4++) {
        float4 w = wr[k4];
        int k = k4 * 4;
        float4 x0 = *(const float4*)(&s_in[k + 0][bg * 4]);
        float4 x1 = *(const float4*)(&s_in[k + 1][bg * 4]);
        float4 x2 = *(const float4*)(&s_in[k + 2][bg * 4]);
        float4 x3 = *(const float4*)(&s_in[k + 3][bg * 4]);
        acc[0] += w.x*x0.x + w.y*x1.x + w.z*x2.x + w.w*x3.x;
        acc[1] += w.x*x0.y + w.y*x1.y + w.z*x2.y + w.w*x3.y;
        acc[2] += w.x*x0.z + w.y*x1.z + w.z*x2.z + w.w*x3.z;
        acc[3] += w.x*x0.w + w.y*x1.w + w.z*x2.w + w.w*x3.w;
    }
    const float4* wr2 = (const float4*)(whh + (size_t)j * 128);
    #pragma unroll 8
    for (int k4 = 0; k4 < 32; k4++) {
        float4 w = wr2[k4];
        int k = k4 * 4;
        float4 x0 = *(const float4*)(&s_h[k + 0][bg * 4]);
        float4 x1 = *(const float4*)(&s_h[k + 1][bg * 4]);
        float4 x2 = *(const float4*)(&s_h[k + 2][bg * 4]);
        float4 x3 = *(const float4*)(&s_h[k + 3][bg * 4]);
        acc[0] += w.x*x0.x + w.y*x1.x + w.z*x2.x + w.w*x3.x;
        acc[1] += w.x*x0.y + w.y*x1.y + w.z*x2.y + w.w*x3.y;
        acc[2] += w.x*x0.z + w.y*x1.z + w.z*x2.z + w.w*x3.z;
        acc[3] += w.x*x0.w + w.y*x1.w + w.z*x2.w + w.w*x3.w;
    }
    float bias = bih[j] + bhh[j];
    s_g[bg * 4 + 0][col] = acc[0] + bias;
    s_g[bg * 4 + 1][col] = acc[1] + bias;
    s_g[bg * 4 + 2][col] = acc[2] + bias;
    s_g[bg * 4 + 3][col] = acc[3] + bias;
    __syncthreads();

    {   // cell update: 16b x 16k
        int bb = tid >> 4, k2 = tid & 15;
        float gi = s_g[bb][ 0 + k2], gf = s_g[bb][16 + k2];
        float gg = s_g[bb][32 + k2], go = s_g[bb][48 + k2];
        int idx = (b0 + bb) * H1n + kt * 16 + k2;
        float c = sigm(gf) * g_c1[idx] + sigm(gi) * tanhf(gg);
        g_c1[idx] = c;
        h1out[idx] = sigm(go) * tanhf(c);
    }
}

// ---------------- LSTM2: gates + cell, writes h2 into g_h2 and g_x ----------
// grid 32 (b-tiles of 8), 256 threads (one per gate column)
__global__ void k_lstm2(const float* __restrict__ wih, const float* __restrict__ whh,
                        const float* __restrict__ bih, const float* __restrict__ bhh,
                        int ph) {
    __shared__ float s_c[192][8];     // [k][b]  (h1_new | h2_old)
    __shared__ float s_g[8][256];
    const float* __restrict__ h1new = g_h1[ph ^ 1];
    int b0 = blockIdx.x * 8;
    int tid = threadIdx.x;

    for (int idx = tid; idx < 8 * 192; idx += 256) {
        int bb = idx / 192, k = idx - bb * 192;
        float v = (k < H1n) ? h1new[(b0 + bb) * H1n + k]
                            : g_h2[(b0 + bb) * H2n + (k - H1n)];
        s_c[k][bb] = v;
    }
    __syncthreads();

    int j = tid;
    float acc[8] = {0,0,0,0,0,0,0,0};
    const float4* wr = (const float4*)(wih + (size_t)j * 128);
    #pragma unroll 4
    for (int k4 = 0; k4 < 32; k4++) {
        float4 w = wr[k4];
        float wl[4] = {w.x, w.y, w.z, w.w};
        #pragma unroll
        for (int kk = 0; kk < 4; kk++) {
            int k = k4 * 4 + kk;
            float4 xa = *(const float4*)(&s_c[k][0]);
            float4 xb = *(const float4*)(&s_c[k][4]);
            acc[0] += wl[kk]*xa.x; acc[1] += wl[kk]*xa.y;
            acc[2] += wl[kk]*xa.z; acc[3] += wl[kk]*xa.w;
            acc[4] += wl[kk]*xb.x; acc[5] += wl[kk]*xb.y;
            acc[6] += wl[kk]*xb.z; acc[7] += wl[kk]*xb.w;
        }
    }
    const float4* wr2 = (const float4*)(whh + (size_t)j * 64);
    #pragma unroll 4
    for (int k4 = 0; k4 < 16; k4++) {
        float4 w = wr2[k4];
        float wl[4] = {w.x, w.y, w.z, w.w};
        #pragma unroll
        for (int kk = 0; kk < 4; kk++) {
            int k = 128 + k4 * 4 + kk;
            float4 xa = *(const float4*)(&s_c[k][0]);
            float4 xb = *(const float4*)(&s_c[k][4]);
            acc[0] += wl[kk]*xa.x; acc[1] += wl[kk]*xa.y;
            acc[2] += wl[kk]*xa.z; acc[3] += wl[kk]*xa.w;
            acc[4] += wl[kk]*xb.x; acc[5] += wl[kk]*xb.y;
            acc[6] += wl[kk]*xb.z; acc[7] += wl[kk]*xb.w;
        }
    }
    float bias = bih[j] + bhh[j];
    #pragma unroll
    for (int i = 0; i < 8; i++) s_g[i][j] = acc[i] + bias;
    __syncthreads();

    for (int idx = tid; idx < 8 * 64; idx += 256) {
        int bb = idx >> 6, k2 = idx & 63;
        float gi = s_g[bb][k2],        gf = s_g[bb][ 64 + k2];
        float gg = s_g[bb][128 + k2],  go = s_g[bb][192 + k2];
        int gidx = (b0 + bb) * H2n + k2;
        float c = sigm(gf) * g_c2[gidx] + sigm(gi) * tanhf(gg);
        g_c2[gidx] = c;
        float h = sigm(go) * tanhf(c);
        g_h2[gidx] = h;
        g_x[(b0 + bb) * (H2n + Dn) + k2] = h;
    }
}

// ---------------- attention: query + energy + masked softmax + context ------
// grid 256 (one block per batch row), 256 threads. Also zeroes g_amax[b].
__global__ void k_attn(const float* __restrict__ wq, const float* __restrict__ bq,
                       const float* __restrict__ enc_key, const float* __restrict__ enc_val,
                       const int* __restrict__ mask) {
    __shared__ float s_q[64], s_h2[64], s_e[512], s_w[512], s_red[64], s_p[256];
    int b = blockIdx.x, tid = threadIdx.x;
    if (tid == 0) g_amax[b] = 0ull;
    if (tid < 64) s_h2[tid] = g_h2[b * H2n + tid];
    __syncthreads();
    if (tid < 64) {
        float a = bq[tid];
        const float* w = wq + tid * H2n;
        #pragma unroll
        for (int k = 0; k < 64; k++) a += w[k] * s_h2[k];
        s_q[tid] = a;
    }
    __syncthreads();

    int warp = tid >> 5, lane = tid & 31;
    float q0 = s_q[2 * lane], q1 = s_q[2 * lane + 1];
    #pragma unroll 4
    for (int it = 0; it < 64; it++) {
        int t = it * 8 + warp;
        float2 kv = *(const float2*)(enc_key + (size_t)t * Bn * Dn + b * Dn + 2 * lane);
        float p = q0 * kv.x + q1 * kv.y;
        p += __shfl_down_sync(0xffffffffu, p, 16);
        p += __shfl_down_sync(0xffffffffu, p, 8);
        p += __shfl_down_sync(0xffffffffu, p, 4);
        p += __shfl_down_sync(0xffffffffu, p, 2);
        p += __shfl_down_sync(0xffffffffu, p, 1);
        if (lane == 0) s_e[t] = p;
    }
    __syncthreads();

    float m = fmaxf(s_e[tid], s_e[tid + 256]);
    for (int o = 16; o; o >>= 1) m = fmaxf(m, __shfl_down_sync(0xffffffffu, m, o));
    if (lane == 0) s_red[warp] = m;
    __syncthreads();
    if (tid == 0) {
        float mm = s_red[0];
        for (int i = 1; i < 8; i++) mm = fmaxf(mm, s_red[i]);
        s_red[32] = mm;
    }
    __syncthreads();
    float mx = s_red[32];
    float e0 = expf(s_e[tid] - mx), e1 = expf(s_e[tid + 256] - mx);
    int m0 = mask[b * Tn + tid], m1 = mask[b * Tn + tid + 256];
    float s  = e0 + e1;
    float ws = (m0 ? e0 : 0.f) + (m1 ? e1 : 0.f);
    for (int o = 16; o; o >>= 1) {
        s  += __shfl_down_sync(0xffffffffu, s,  o);
        ws += __shfl_down_sync(0xffffffffu, ws, o);
    }
    if (lane == 0) { s_red[warp] = s; s_red[8 + warp] = ws; }
    __syncthreads();
    if (tid == 0) {
        float S = 0.f, WS = 0.f;
        for (int i = 0; i < 8; i++) { S += s_red[i]; WS += s_red[8 + i]; }
        s_red[33] = 1.0f / (S * fmaxf(WS / S, 2e-30f));  // mask*e*inv == m_att/denom
    }
    __syncthreads();
    float inv = s_red[33];
    s_w[tid]       = m0 ? e0 * inv : 0.f;
    s_w[tid + 256] = m1 ? e1 * inv : 0.f;
    __syncthreads();

    int d = tid & 63, ch = tid >> 6;
    float a0 = 0.f, a1 = 0.f;
    const float* vb = enc_val + (size_t)b * Dn + d;
    #pragma unroll 4
    for (int t = ch * 128; t < ch * 128 + 128; t += 2) {
        a0 += s_w[t]     * vb[(size_t)t * (Bn * Dn)];
        a1 += s_w[t + 1] * vb[(size_t)(t + 1) * (Bn * Dn)];
    }
    s_p[ch * 64 + d] = a0 + a1;
    __syncthreads();
    if (tid < 64) {
        float c = s_p[tid] + s_p[64 + tid] + s_p[128 + tid] + s_p[192 + tid];
        g_ctx[b * Dn + tid] = c;
        g_x[b * (H2n + Dn) + H2n + tid] = c;
    }
}

// ---------------- pred GEMM: [h2|ctx] @ wp^T + bp, fused argmax -------------
// grid (157 v-tiles of 64, 4 b-tiles of 64), 256 threads, 4x4 register tiles
__global__ void k_pred(const float* __restrict__ wp, const float* __restrict__ bp,
                       float* __restrict__ out, int step) {
    __shared__ float s_x[128][68];   // [k][b], padded for LDS.128 alignment
    int vt = blockIdx.x, bt = blockIdx.y;
    int b0 = bt * 64;
    int tid = threadIdx.x;

    for (int idx = tid; idx < 64 * 128; idx += 256) {
        int bb = idx >> 7, k = idx & 127;
        s_x[k][bb] = g_x[(b0 + bb) * 128 + k];
    }
    __syncthreads();

    int vg = tid & 15, bg = tid >> 4;
    int v0 = vt * 64 + vg * 4;
    bool vok = (v0 + 3) < Vn;           // Vn % 4 == 0
    int vl = vok ? v0 : 0;
    const float4* w0 = (const float4*)(wp + (size_t)(vl + 0) * 128);
    const float4* w1 = (const float4*)(wp + (size_t)(vl + 1) * 128);
    const float4* w2 = (const float4*)(wp + (size_t)(vl + 2) * 128);
    const float4* w3 = (const float4*)(wp + (size_t)(vl + 3) * 128);
    int bb0 = bg * 4;

    float acc[4][4];
    #pragma unroll
    for (int i = 0; i < 4; i++)
        #pragma unroll
        for (int jj = 0; jj < 4; jj++) acc[i][jj] = 0.f;

    #pragma unroll 4
    for (int k4 = 0; k4 < 32; k4++) {
        float4 wa = w0[k4], wb = w1[k4], wc = w2[k4], wd = w3[k4];
        float wA[4] = {wa.x, wa.y, wa.z, wa.w};
        float wB[4] = {wb.x, wb.y, wb.z, wb.w};
        float wC[4] = {wc.x, wc.y, wc.z, wc.w};
        float wD[4] = {wd.x, wd.y, wd.z, wd.w};
        #pragma unroll
        for (int kk = 0; kk < 4; kk++) {
            int k = k4 * 4 + kk;
            float4 x = *(const float4*)(&s_x[k][bb0]);
            acc[0][0] += x.x * wA[kk]; acc[0][1] += x.x * wB[kk];
            acc[0][2] += x.x * wC[kk]; acc[0][3] += x.x * wD[kk];
            acc[1][0] += x.y * wA[kk]; acc[1][1] += x.y * wB[kk];
            acc[1][2] += x.y * wC[kk]; acc[1][3] += x.y * wD[kk];
            acc[2][0] += x.z * wA[kk]; acc[2][1] += x.z * wB[kk];
            acc[2][2] += x.z * wC[kk]; acc[2][3] += x.z * wD[kk];
            acc[3][0] += x.w * wA[kk]; acc[3][1] += x.w * wB[kk];
            acc[3][2] += x.w * wC[kk]; acc[3][3] += x.w * wD[kk];
        }
    }

    float b0v = vok ? bp[v0] : 0.f, b1v = vok ? bp[v0 + 1] : 0.f;
    float b2v = vok ? bp[v0 + 2] : 0.f, b3v = vok ? bp[v0 + 3] : 0.f;

    #pragma unroll
    for (int i = 0; i < 4; i++) {
        int bi = b0 + bb0 + i;
        float r0 = acc[i][0] + b0v, r1 = acc[i][1] + b1v;
        float r2 = acc[i][2] + b2v, r3 = acc[i][3] + b3v;
        if (vok) {
            *(float4*)(out + (size_t)bi * ML * Vn + (size_t)step * Vn + v0)
                = make_float4(r0, r1, r2, r3);
        }
        float best = r0; int bv = v0;
        if (r1 > best) { best = r1; bv = v0 + 1; }
        if (r2 > best) { best = r2; bv = v0 + 2; }
        if (r3 > best) { best = r3; bv = v0 + 3; }
        unsigned long long pk = vok
            ? ((unsigned long long)fkey(best) << 32) | (unsigned int)(~bv)
            : 0ull;
        #pragma unroll
        for (int o = 8; o; o >>= 1) {
            unsigned long long other = __shfl_down_sync(0xffffffffu, pk, o, 16);
            if (other > pk) pk = other;
        }
        if (vg == 0) atomicMax(&g_amax[bi], pk);
    }
}

// ---------------- host: graph-capturable launch sequence --------------------
extern "C" void kernel_launch(void* const* d_in, const int* in_sizes, int n_in,
                              void* d_out, int out_size) {
    const float* enc_key = (const float*)d_in[0];
    const float* enc_val = (const float*)d_in[1];
    const int*   mask    = (const int*)d_in[2];
    const float* emb     = (const float*)d_in[3];
    const float* w_ih1   = (const float*)d_in[4];
    const float* w_hh1   = (const float*)d_in[5];
    const float* b_ih1   = (const float*)d_in[6];
    const float* b_hh1   = (const float*)d_in[7];
    const float* w_ih2   = (const float*)d_in[8];
    const float* w_hh2   = (const float*)d_in[9];
    const float* b_ih2   = (const float*)d_in[10];
    const float* b_hh2   = (const float*)d_in[11];
    const float* wq      = (const float*)d_in[12];
    const float* bq      = (const float*)d_in[13];
    const float* wp      = (const float*)d_in[14];
    const float* bp      = (const float*)d_in[15];
    float* out = (float*)d_out;

    k_init<<<128, 256>>>();
    for (int s = 0; s < ML; s++) {
        int ph = s & 1;
        k_lstm1<<<dim3(8, 16), 256>>>(w_ih1, w_hh1, b_ih1, b_hh1, emb, ph);
        k_lstm2<<<32, 256>>>(w_ih2, w_hh2, b_ih2, b_hh2, ph);
        k_attn<<<256, 256>>>(wq, bq, enc_key, enc_val, mask);
        k_pred<<<dim3(157, 4), 256>>>(wp, bp, out, s);
    }
}